// round 1
// baseline (speedup 1.0000x reference)
#include <cuda_runtime.h>
#include <math.h>

#define T_SEQ 2048
#define BATCH 2
#define CDIM  2048
#define HEADS 16
#define HD    128
#define DSTD  120
#define RLOW  8
#define FDIM  6144

// ---------------- scratch (device globals; no allocations) ----------------
__device__ float g_fused[(size_t)BATCH * T_SEQ * FDIM];   // [B*T, 6144]  ~100MB
__device__ float g_Q[(size_t)BATCH * HEADS * T_SEQ * HD]; // [B,H,T,128]
__device__ float g_K[(size_t)BATCH * HEADS * T_SEQ * HD];
__device__ float g_att[(size_t)BATCH * T_SEQ * CDIM];     // [B,T,C]

// ---------------- SGEMM: C[M,N] = A[M,K] * B[N,K]^T (all row-major) -------
__global__ void __launch_bounds__(256, 2)
sgemm_abt(const float* __restrict__ A, const float* __restrict__ B,
          float* __restrict__ C, int M, int N, int K) {
    __shared__ float As[8][128];
    __shared__ float Bs[8][128];

    const int tid = threadIdx.x;
    const int tx = tid & 15;     // 0..15 -> N micro
    const int ty = tid >> 4;     // 0..15 -> M micro
    const int m0 = blockIdx.y << 7;
    const int n0 = blockIdx.x << 7;

    const int lr = tid >> 1;          // 0..127 (tile row)
    const int lk = (tid & 1) << 2;    // 0 or 4 (k offset)
    const float* Ag = A + (size_t)(m0 + lr) * K + lk;
    const float* Bg = B + (size_t)(n0 + lr) * K + lk;

    float acc[8][8];
#pragma unroll
    for (int u = 0; u < 8; u++)
#pragma unroll
        for (int v = 0; v < 8; v++) acc[u][v] = 0.f;

    for (int k0 = 0; k0 < K; k0 += 8) {
        float4 a = *(const float4*)(Ag + k0);
        float4 b = *(const float4*)(Bg + k0);
        __syncthreads();
        As[lk + 0][lr] = a.x; As[lk + 1][lr] = a.y;
        As[lk + 2][lr] = a.z; As[lk + 3][lr] = a.w;
        Bs[lk + 0][lr] = b.x; Bs[lk + 1][lr] = b.y;
        Bs[lk + 2][lr] = b.z; Bs[lk + 3][lr] = b.w;
        __syncthreads();
#pragma unroll
        for (int k = 0; k < 8; k++) {
            float4 a0 = *(const float4*)&As[k][ty << 3];
            float4 a1 = *(const float4*)&As[k][(ty << 3) + 4];
            float4 b0 = *(const float4*)&Bs[k][tx << 3];
            float4 b1 = *(const float4*)&Bs[k][(tx << 3) + 4];
            float av[8] = {a0.x, a0.y, a0.z, a0.w, a1.x, a1.y, a1.z, a1.w};
            float bv[8] = {b0.x, b0.y, b0.z, b0.w, b1.x, b1.y, b1.z, b1.w};
#pragma unroll
            for (int u = 0; u < 8; u++)
#pragma unroll
                for (int v = 0; v < 8; v++)
                    acc[u][v] = fmaf(av[u], bv[v], acc[u][v]);
        }
    }

#pragma unroll
    for (int u = 0; u < 8; u++) {
        float* Cr = C + (size_t)(m0 + (ty << 3) + u) * N + n0 + (tx << 3);
        float4 c0 = make_float4(acc[u][0], acc[u][1], acc[u][2], acc[u][3]);
        float4 c1 = make_float4(acc[u][4], acc[u][5], acc[u][6], acc[u][7]);
        *(float4*)Cr = c0;
        *(float4*)(Cr + 4) = c1;
    }
}

// ---------------- Build Qf/Kf with per-head routing ------------------------
__global__ void build_qk(const float* __restrict__ fused,
                         const float* __restrict__ w_std,
                         const float* __restrict__ w_rec,
                         float* __restrict__ Qf, float* __restrict__ Kf) {
    int idx = blockIdx.x * blockDim.x + threadIdx.x; // total B*H*T*HD = 8388608
    int d = idx & 127;
    int t = (idx >> 7) & (T_SEQ - 1);
    int h = (idx >> 18) & 15;
    int b = idx >> 22;

    float wsv = w_std[h];
    float wrv = w_rec[h];
    float ws = sqrtf(fmaxf(wsv, 1e-8f));
    float wr = sqrtf(fmaxf(wrv, 1e-8f));
    bool ra = (wrv > 0.1f);

    size_t frow = ((size_t)(b * T_SEQ + t)) * FDIM;
    float q, k;
    if (d < DSTD) {
        q = ws * fused[frow + h * DSTD + d];
        k = ws * fused[frow + (HEADS * DSTD) + h * DSTD + d];
    } else {
        int r = d - DSTD;
        float ql = fused[frow + 5888 + h * RLOW + r];
        float kl = fused[frow + 6016 + h * RLOW + r];
        q = ra ? wr * kl : ws * ql;
        k = ra ? wr * ql : ws * kl;
    }
    Qf[idx] = q;
    Kf[idx] = k;
}

// ---------------- Causal flash attention (fp32) ---------------------------
// Q,K: [B*H, T, 128]; V read in-place from fused at offset 3840 + h*128.
// Block: 64 queries x full D=128, key tiles of 64. 256 threads (16x16).
__global__ void __launch_bounds__(256, 1)
attn_kernel(const float* __restrict__ Q, const float* __restrict__ Kf,
            const float* __restrict__ fused, float* __restrict__ out) {
    extern __shared__ float sm[];
    float* QsT = sm;             // [128][64]
    float* KsT = sm + 8192;      // [128][64]
    float* Vs  = sm + 16384;     // [64][128]
    float* PsT = sm + 24576;     // [64][68]

    const int tid = threadIdx.x;
    const int tx = tid & 15;
    const int ty = tid >> 4;
    const int bh = blockIdx.y;
    const int b = bh >> 4;
    const int h = bh & 15;
    const int q0 = blockIdx.x << 6;

    // load Q tile transposed: QsT[d][i]
    const float* Qg = Q + ((size_t)bh * T_SEQ + q0) * HD;
#pragma unroll
    for (int it = 0; it < 8; it++) {
        int idx = tid + it * 256;  // 0..2047
        int i = idx >> 5;          // row 0..63
        int d4 = idx & 31;         // float4 along d
        float4 v = *(const float4*)(Qg + (size_t)i * HD + (d4 << 2));
        QsT[(d4 * 4 + 0) * 64 + i] = v.x;
        QsT[(d4 * 4 + 1) * 64 + i] = v.y;
        QsT[(d4 * 4 + 2) * 64 + i] = v.z;
        QsT[(d4 * 4 + 3) * 64 + i] = v.w;
    }

    float acc[4][8];
    float mrow[4], lrow[4];
#pragma unroll
    for (int u = 0; u < 4; u++) {
        mrow[u] = -INFINITY;
        lrow[u] = 0.f;
#pragma unroll
        for (int w = 0; w < 8; w++) acc[u][w] = 0.f;
    }

    const float scale = 0.08838834764831845f;  // 1/sqrt(128)

    for (int k0 = 0; k0 <= q0; k0 += 64) {
        const float* Kg = Kf + ((size_t)bh * T_SEQ + k0) * HD;
        const float* Vg = fused + ((size_t)(b * T_SEQ + k0)) * FDIM + 3840 + h * HD;
        __syncthreads();
#pragma unroll
        for (int it = 0; it < 8; it++) {
            int idx = tid + it * 256;
            int i = idx >> 5;
            int d4 = idx & 31;
            float4 kv = *(const float4*)(Kg + (size_t)i * HD + (d4 << 2));
            KsT[(d4 * 4 + 0) * 64 + i] = kv.x;
            KsT[(d4 * 4 + 1) * 64 + i] = kv.y;
            KsT[(d4 * 4 + 2) * 64 + i] = kv.z;
            KsT[(d4 * 4 + 3) * 64 + i] = kv.w;
            float4 vv = *(const float4*)(Vg + (size_t)i * FDIM + (d4 << 2));
            *(float4*)&Vs[i * 128 + (d4 << 2)] = vv;
        }
        __syncthreads();

        // S = Q K^T (64x64), micro 4x4 per thread
        float s[4][4];
#pragma unroll
        for (int u = 0; u < 4; u++)
#pragma unroll
            for (int v = 0; v < 4; v++) s[u][v] = 0.f;

#pragma unroll 4
        for (int d = 0; d < 128; d++) {
            float4 qa = *(const float4*)&QsT[d * 64 + (ty << 2)];
            float4 kb = *(const float4*)&KsT[d * 64 + (tx << 2)];
            float qv[4] = {qa.x, qa.y, qa.z, qa.w};
            float kvv[4] = {kb.x, kb.y, kb.z, kb.w};
#pragma unroll
            for (int u = 0; u < 4; u++)
#pragma unroll
                for (int v = 0; v < 4; v++)
                    s[u][v] = fmaf(qv[u], kvv[v], s[u][v]);
        }

        // mask + online softmax (row stats replicated across the 16-lane group)
#pragma unroll
        for (int u = 0; u < 4; u++) {
            int qq = q0 + (ty << 2) + u;
            float rmax = -INFINITY;
#pragma unroll
            for (int v = 0; v < 4; v++) {
                int kk = k0 + (tx << 2) + v;
                float val = (kk <= qq) ? s[u][v] * scale : -INFINITY;
                s[u][v] = val;
                rmax = fmaxf(rmax, val);
            }
#pragma unroll
            for (int off = 8; off; off >>= 1)
                rmax = fmaxf(rmax, __shfl_xor_sync(0xffffffffu, rmax, off, 16));
            float mn = fmaxf(mrow[u], rmax);
            float al = __expf(mrow[u] - mn);
            mrow[u] = mn;
            float rs = 0.f;
#pragma unroll
            for (int v = 0; v < 4; v++) {
                float p = __expf(s[u][v] - mn);
                s[u][v] = p;
                rs += p;
            }
#pragma unroll
            for (int off = 8; off; off >>= 1)
                rs += __shfl_xor_sync(0xffffffffu, rs, off, 16);
            lrow[u] = lrow[u] * al + rs;
#pragma unroll
            for (int w = 0; w < 8; w++) acc[u][w] *= al;
        }

        // P transposed into smem: PsT[j][i] (stride 68 keeps 16B alignment)
#pragma unroll
        for (int u = 0; u < 4; u++)
#pragma unroll
            for (int v = 0; v < 4; v++)
                PsT[((tx << 2) + v) * 68 + (ty << 2) + u] = s[u][v];
        __syncthreads();

        // O += P * V ; micro 4x8 per thread
#pragma unroll 2
        for (int j = 0; j < 64; j++) {
            float4 pa = *(const float4*)&PsT[j * 68 + (ty << 2)];
            float4 vb0 = *(const float4*)&Vs[j * 128 + (tx << 3)];
            float4 vb1 = *(const float4*)&Vs[j * 128 + (tx << 3) + 4];
            float pv[4] = {pa.x, pa.y, pa.z, pa.w};
            float vv[8] = {vb0.x, vb0.y, vb0.z, vb0.w, vb1.x, vb1.y, vb1.z, vb1.w};
#pragma unroll
            for (int u = 0; u < 4; u++)
#pragma unroll
                for (int w = 0; w < 8; w++)
                    acc[u][w] = fmaf(pv[u], vv[w], acc[u][w]);
        }
    }

    // epilogue: divide by l and write [B,T,H*D] so GEMM2 consumes [B,T,C]
#pragma unroll
    for (int u = 0; u < 4; u++) {
        float inv = 1.f / lrow[u];
        int qq = q0 + (ty << 2) + u;
        float* orow = out + ((size_t)(b * T_SEQ + qq)) * CDIM + h * HD + (tx << 3);
        float4 o0 = make_float4(acc[u][0] * inv, acc[u][1] * inv,
                                acc[u][2] * inv, acc[u][3] * inv);
        float4 o1 = make_float4(acc[u][4] * inv, acc[u][5] * inv,
                                acc[u][6] * inv, acc[u][7] * inv);
        *(float4*)orow = o0;
        *(float4*)(orow + 4) = o1;
    }
}

// ---------------- launch ---------------------------------------------------
extern "C" void kernel_launch(void* const* d_in, const int* in_sizes, int n_in,
                              void* d_out, int out_size) {
    const float* x      = (const float*)d_in[0];
    const float* W_attn = (const float*)d_in[1];
    const float* W_proj = (const float*)d_in[2];
    const float* w_std  = (const float*)d_in[3];
    const float* w_rec  = (const float*)d_in[4];
    float* out = (float*)d_out;

    float *fused, *Qf, *Kf, *att;
    cudaGetSymbolAddress((void**)&fused, g_fused);
    cudaGetSymbolAddress((void**)&Qf, g_Q);
    cudaGetSymbolAddress((void**)&Kf, g_K);
    cudaGetSymbolAddress((void**)&att, g_att);

    const int M = BATCH * T_SEQ;  // 4096

    // GEMM1: fused = x * W_attn^T   [4096,6144]
    {
        dim3 grid(FDIM / 128, M / 128);
        sgemm_abt<<<grid, 256>>>(x, W_attn, fused, M, FDIM, CDIM);
    }
    // pack Qf/Kf with routing
    {
        int total = BATCH * HEADS * T_SEQ * HD;
        build_qk<<<total / 256, 256>>>(fused, w_std, w_rec, Qf, Kf);
    }
    // causal attention
    {
        size_t smem = (size_t)(8192 + 8192 + 8192 + 64 * 68) * sizeof(float);
        cudaFuncSetAttribute(attn_kernel,
                             cudaFuncAttributeMaxDynamicSharedMemorySize,
                             (int)smem);
        dim3 grid(T_SEQ / 64, BATCH * HEADS);
        attn_kernel<<<grid, 256, smem>>>(Qf, Kf, fused, att);
    }
    // GEMM2: out = att * W_proj^T   [4096,2048]
    {
        dim3 grid(CDIM / 128, M / 128);
        sgemm_abt<<<grid, 256>>>(att, W_proj, out, M, CDIM, CDIM);
    }
}

// round 3
// speedup vs baseline: 2.1217x; 2.1217x over previous
#include <cuda_runtime.h>
#include <cuda_fp16.h>
#include <math.h>
#include <stdint.h>

#define T_SEQ 2048
#define BATCH 2
#define CDIM  2048
#define HEADS 16
#define HD    128
#define DSTD  120
#define RLOW  8
#define FDIM  6144

// ---------------- scratch (device globals; no allocations) ----------------
__device__ float g_fused[(size_t)BATCH * T_SEQ * FDIM];
__device__ float g_Q[(size_t)BATCH * HEADS * T_SEQ * HD];
__device__ float g_K[(size_t)BATCH * HEADS * T_SEQ * HD];
__device__ __align__(16) __half g_xh[(size_t)BATCH * T_SEQ * CDIM];
__device__ __align__(16) __half g_Wah[(size_t)FDIM * CDIM];
__device__ __align__(16) __half g_Wph[(size_t)CDIM * CDIM];
__device__ __align__(16) __half g_atth[(size_t)BATCH * T_SEQ * CDIM];

// ---------------- PTX helpers ----------------------------------------------
__device__ __forceinline__ uint32_t smem_u32(const void* p) {
    uint32_t a;
    asm("{ .reg .u64 t; cvta.to.shared.u64 t, %1; cvt.u32.u64 %0, t; }"
        : "=r"(a) : "l"(p));
    return a;
}
__device__ __forceinline__ void cp16(uint32_t saddr, const void* gaddr) {
    asm volatile("cp.async.cg.shared.global [%0], [%1], 16;"
                 :: "r"(saddr), "l"(gaddr) : "memory");
}
__device__ __forceinline__ void ldsm_x4(uint32_t* r, uint32_t addr) {
    asm volatile("ldmatrix.sync.aligned.m8n8.x4.shared.b16 {%0,%1,%2,%3}, [%4];"
                 : "=r"(r[0]), "=r"(r[1]), "=r"(r[2]), "=r"(r[3]) : "r"(addr));
}
__device__ __forceinline__ void mma16816(float* c, const uint32_t* a,
                                         uint32_t b0, uint32_t b1) {
    asm volatile(
        "mma.sync.aligned.m16n8k16.row.col.f32.f16.f16.f32 "
        "{%0,%1,%2,%3},{%4,%5,%6,%7},{%8,%9},{%0,%1,%2,%3};"
        : "+f"(c[0]), "+f"(c[1]), "+f"(c[2]), "+f"(c[3])
        : "r"(a[0]), "r"(a[1]), "r"(a[2]), "r"(a[3]), "r"(b0), "r"(b1));
}

// ---------------- HMMA GEMM: C[M,N]=A[M,K]*B[N,K]^T (fp16 in, fp32 out) ----
// 128x128 tile, BK=64 (128B rows, SW128 swizzle), 3-stage cp.async, 8 warps.
#define GSMEM (3 * 32768)

__global__ void __launch_bounds__(256, 2)
hgemm_mma(const __half* __restrict__ A, const __half* __restrict__ B,
          float* __restrict__ C, int M, int N, int K) {
    extern __shared__ __align__(1024) char smem_raw[];
    const uint32_t smem = smem_u32(smem_raw);
    const int tid = threadIdx.x;
    const int wid = tid >> 5;
    const int lid = tid & 31;
    const int m0 = blockIdx.y << 7;
    const int n0 = blockIdx.x << 7;
    const int wm0 = (wid & 1) << 6;   // 0 or 64
    const int wn0 = (wid >> 1) << 5;  // 0,32,64,96

    const int r = tid >> 1;
    const int hs = tid & 1;
    const __half* Ag = A + (size_t)(m0 + r) * K + hs * 32;
    const __half* Bg = B + (size_t)(n0 + r) * K + hs * 32;
    const uint32_t swb = r * 128 + hs * 64;

    auto load_stage = [&](int kt, int s) {
        uint32_t ab = smem + s * 32768;
        uint32_t bb = ab + 16384;
        const __half* ag = Ag + kt * 64;
        const __half* bg = Bg + kt * 64;
#pragma unroll
        for (int j = 0; j < 4; j++) {
            uint32_t off = swb + j * 16;
            uint32_t sw = off ^ ((off >> 3) & 0x70);
            cp16(ab + sw, ag + j * 8);
            cp16(bb + sw, bg + j * 8);
        }
        asm volatile("cp.async.commit_group;" ::: "memory");
    };

    float acc[4][4][4];
#pragma unroll
    for (int mt = 0; mt < 4; mt++)
#pragma unroll
        for (int nt = 0; nt < 4; nt++)
#pragma unroll
            for (int e = 0; e < 4; e++) acc[mt][nt][e] = 0.f;

    const int KT = K >> 6;
    load_stage(0, 0);
    load_stage(1, 1);

    const int grp = lid >> 3;
    const int lr = lid & 7;
    const int arow = wm0 + ((grp & 1) << 3) + lr;
    const int acol = (grp >> 1) << 3;
    const int brow = wn0 + ((grp & 1) << 3) + lr;

    for (int kt = 0; kt < KT; kt++) {
        const int s = kt % 3;
        asm volatile("cp.async.wait_group 1;" ::: "memory");
        __syncthreads();
        if (kt + 2 < KT) load_stage(kt + 2, (kt + 2) % 3);
        const uint32_t ab = smem + s * 32768;
        const uint32_t bb = ab + 16384;
#pragma unroll
        for (int ks = 0; ks < 4; ks++) {
            uint32_t a_regs[4][4];
#pragma unroll
            for (int mt = 0; mt < 4; mt++) {
                uint32_t off = (uint32_t)(arow + mt * 16) * 128 + (acol + ks * 16) * 2;
                uint32_t sw = off ^ ((off >> 3) & 0x70);
                ldsm_x4(a_regs[mt], ab + sw);
            }
            uint32_t b_regs[2][4];
#pragma unroll
            for (int np = 0; np < 2; np++) {
                uint32_t off = (uint32_t)(brow + np * 16) * 128 + (acol + ks * 16) * 2;
                uint32_t sw = off ^ ((off >> 3) & 0x70);
                ldsm_x4(b_regs[np], bb + sw);
            }
#pragma unroll
            for (int mt = 0; mt < 4; mt++)
#pragma unroll
                for (int nt = 0; nt < 4; nt++) {
                    uint32_t b0 = b_regs[nt >> 1][nt & 1];
                    uint32_t b1 = b_regs[nt >> 1][(nt & 1) + 2];
                    mma16816(acc[mt][nt], a_regs[mt], b0, b1);
                }
        }
    }

    // epilogue: direct register stores (float2 per fragment row)
    const int row0 = m0 + wm0 + (lid >> 2);
    const int col0 = n0 + wn0 + (lid & 3) * 2;
#pragma unroll
    for (int mt = 0; mt < 4; mt++)
#pragma unroll
        for (int nt = 0; nt < 4; nt++) {
            float* p0 = C + (size_t)(row0 + mt * 16) * N + col0 + nt * 8;
            float* p1 = C + (size_t)(row0 + mt * 16 + 8) * N + col0 + nt * 8;
            *(float2*)p0 = make_float2(acc[mt][nt][0], acc[mt][nt][1]);
            *(float2*)p1 = make_float2(acc[mt][nt][2], acc[mt][nt][3]);
        }
}

// ---------------- fp32 -> fp16 conversion ----------------------------------
__global__ void f2h(const float* __restrict__ in, __half* __restrict__ out, int n4) {
    int i = blockIdx.x * blockDim.x + threadIdx.x;
    if (i < n4) {
        float4 v = ((const float4*)in)[i];
        ((__half2*)out)[2 * i] = __floats2half2_rn(v.x, v.y);
        ((__half2*)out)[2 * i + 1] = __floats2half2_rn(v.z, v.w);
    }
}

// ---------------- Build Qf/Kf with per-head routing ------------------------
__global__ void build_qk(const float* __restrict__ fused,
                         const float* __restrict__ w_std,
                         const float* __restrict__ w_rec,
                         float* __restrict__ Qf, float* __restrict__ Kf) {
    int idx = blockIdx.x * blockDim.x + threadIdx.x;
    int d = idx & 127;
    int t = (idx >> 7) & (T_SEQ - 1);
    int h = (idx >> 18) & 15;
    int b = idx >> 22;

    float wsv = w_std[h];
    float wrv = w_rec[h];
    float ws = sqrtf(fmaxf(wsv, 1e-8f));
    float wr = sqrtf(fmaxf(wrv, 1e-8f));
    bool ra = (wrv > 0.1f);

    size_t frow = ((size_t)(b * T_SEQ + t)) * FDIM;
    float q, k;
    if (d < DSTD) {
        q = ws * fused[frow + h * DSTD + d];
        k = ws * fused[frow + (HEADS * DSTD) + h * DSTD + d];
    } else {
        int rr = d - DSTD;
        float ql = fused[frow + 5888 + h * RLOW + rr];
        float kl = fused[frow + 6016 + h * RLOW + rr];
        q = ra ? wr * kl : ws * ql;
        k = ra ? wr * ql : ws * kl;
    }
    Qf[idx] = q;
    Kf[idx] = k;
}

// ---------------- Causal flash attention (fp32, fp16 output) ---------------
__global__ void __launch_bounds__(256, 1)
attn_kernel(const float* __restrict__ Q, const float* __restrict__ Kf,
            const float* __restrict__ fused, __half* __restrict__ out) {
    extern __shared__ float sm[];
    float* QsT = sm;
    float* KsT = sm + 8192;
    float* Vs  = sm + 16384;
    float* PsT = sm + 24576;

    const int tid = threadIdx.x;
    const int tx = tid & 15;
    const int ty = tid >> 4;
    const int bh = blockIdx.y;
    const int b = bh >> 4;
    const int h = bh & 15;
    const int q0 = blockIdx.x << 6;

    const float* Qg = Q + ((size_t)bh * T_SEQ + q0) * HD;
#pragma unroll
    for (int it = 0; it < 8; it++) {
        int idx = tid + it * 256;
        int i = idx >> 5;
        int d4 = idx & 31;
        float4 v = *(const float4*)(Qg + (size_t)i * HD + (d4 << 2));
        QsT[(d4 * 4 + 0) * 64 + i] = v.x;
        QsT[(d4 * 4 + 1) * 64 + i] = v.y;
        QsT[(d4 * 4 + 2) * 64 + i] = v.z;
        QsT[(d4 * 4 + 3) * 64 + i] = v.w;
    }

    float acc[4][8];
    float mrow[4], lrow[4];
#pragma unroll
    for (int u = 0; u < 4; u++) {
        mrow[u] = -INFINITY;
        lrow[u] = 0.f;
#pragma unroll
        for (int w = 0; w < 8; w++) acc[u][w] = 0.f;
    }

    const float scale = 0.08838834764831845f;

    for (int k0 = 0; k0 <= q0; k0 += 64) {
        const float* Kg = Kf + ((size_t)bh * T_SEQ + k0) * HD;
        const float* Vg = fused + ((size_t)(b * T_SEQ + k0)) * FDIM + 3840 + h * HD;
        __syncthreads();
#pragma unroll
        for (int it = 0; it < 8; it++) {
            int idx = tid + it * 256;
            int i = idx >> 5;
            int d4 = idx & 31;
            float4 kv = *(const float4*)(Kg + (size_t)i * HD + (d4 << 2));
            KsT[(d4 * 4 + 0) * 64 + i] = kv.x;
            KsT[(d4 * 4 + 1) * 64 + i] = kv.y;
            KsT[(d4 * 4 + 2) * 64 + i] = kv.z;
            KsT[(d4 * 4 + 3) * 64 + i] = kv.w;
            float4 vv = *(const float4*)(Vg + (size_t)i * FDIM + (d4 << 2));
            *(float4*)&Vs[i * 128 + (d4 << 2)] = vv;
        }
        __syncthreads();

        float s[4][4];
#pragma unroll
        for (int u = 0; u < 4; u++)
#pragma unroll
            for (int v = 0; v < 4; v++) s[u][v] = 0.f;

#pragma unroll 4
        for (int d = 0; d < 128; d++) {
            float4 qa = *(const float4*)&QsT[d * 64 + (ty << 2)];
            float4 kb = *(const float4*)&KsT[d * 64 + (tx << 2)];
            float qv[4] = {qa.x, qa.y, qa.z, qa.w};
            float kvv[4] = {kb.x, kb.y, kb.z, kb.w};
#pragma unroll
            for (int u = 0; u < 4; u++)
#pragma unroll
                for (int v = 0; v < 4; v++)
                    s[u][v] = fmaf(qv[u], kvv[v], s[u][v]);
        }

#pragma unroll
        for (int u = 0; u < 4; u++) {
            int qq = q0 + (ty << 2) + u;
            float rmax = -INFINITY;
#pragma unroll
            for (int v = 0; v < 4; v++) {
                int kk = k0 + (tx << 2) + v;
                float val = (kk <= qq) ? s[u][v] * scale : -INFINITY;
                s[u][v] = val;
                rmax = fmaxf(rmax, val);
            }
#pragma unroll
            for (int off = 8; off; off >>= 1)
                rmax = fmaxf(rmax, __shfl_xor_sync(0xffffffffu, rmax, off, 16));
            float mn = fmaxf(mrow[u], rmax);
            float al = __expf(mrow[u] - mn);
            mrow[u] = mn;
            float rs = 0.f;
#pragma unroll
            for (int v = 0; v < 4; v++) {
                float p = __expf(s[u][v] - mn);
                s[u][v] = p;
                rs += p;
            }
#pragma unroll
            for (int off = 8; off; off >>= 1)
                rs += __shfl_xor_sync(0xffffffffu, rs, off, 16);
            lrow[u] = lrow[u] * al + rs;
#pragma unroll
            for (int w = 0; w < 8; w++) acc[u][w] *= al;
        }

#pragma unroll
        for (int u = 0; u < 4; u++)
#pragma unroll
            for (int v = 0; v < 4; v++)
                PsT[((tx << 2) + v) * 68 + (ty << 2) + u] = s[u][v];
        __syncthreads();

#pragma unroll 2
        for (int j = 0; j < 64; j++) {
            float4 pa = *(const float4*)&PsT[j * 68 + (ty << 2)];
            float4 vb0 = *(const float4*)&Vs[j * 128 + (tx << 3)];
            float4 vb1 = *(const float4*)&Vs[j * 128 + (tx << 3) + 4];
            float pv[4] = {pa.x, pa.y, pa.z, pa.w};
            float vv[8] = {vb0.x, vb0.y, vb0.z, vb0.w, vb1.x, vb1.y, vb1.z, vb1.w};
#pragma unroll
            for (int u = 0; u < 4; u++)
#pragma unroll
                for (int w = 0; w < 8; w++)
                    acc[u][w] = fmaf(pv[u], vv[w], acc[u][w]);
        }
    }

#pragma unroll
    for (int u = 0; u < 4; u++) {
        float inv = 1.f / lrow[u];
        int qq = q0 + (ty << 2) + u;
        __half2* orow = (__half2*)(out + ((size_t)(b * T_SEQ + qq)) * CDIM + h * HD + (tx << 3));
        orow[0] = __floats2half2_rn(acc[u][0] * inv, acc[u][1] * inv);
        orow[1] = __floats2half2_rn(acc[u][2] * inv, acc[u][3] * inv);
        orow[2] = __floats2half2_rn(acc[u][4] * inv, acc[u][5] * inv);
        orow[3] = __floats2half2_rn(acc[u][6] * inv, acc[u][7] * inv);
    }
}

// ---------------- launch ----------------------------------------------------
extern "C" void kernel_launch(void* const* d_in, const int* in_sizes, int n_in,
                              void* d_out, int out_size) {
    const float* x      = (const float*)d_in[0];
    const float* W_attn = (const float*)d_in[1];
    const float* W_proj = (const float*)d_in[2];
    const float* w_std  = (const float*)d_in[3];
    const float* w_rec  = (const float*)d_in[4];
    float* out = (float*)d_out;

    float *fused, *Qf, *Kf;
    __half *xh, *Wah, *Wph, *atth;
    cudaGetSymbolAddress((void**)&fused, g_fused);
    cudaGetSymbolAddress((void**)&Qf, g_Q);
    cudaGetSymbolAddress((void**)&Kf, g_K);
    cudaGetSymbolAddress((void**)&xh, g_xh);
    cudaGetSymbolAddress((void**)&Wah, g_Wah);
    cudaGetSymbolAddress((void**)&Wph, g_Wph);
    cudaGetSymbolAddress((void**)&atth, g_atth);

    const int M = BATCH * T_SEQ;  // 4096

    cudaFuncSetAttribute(hgemm_mma, cudaFuncAttributeMaxDynamicSharedMemorySize, GSMEM);

    // convert inputs to fp16
    {
        int n4 = (M * CDIM) / 4;
        f2h<<<(n4 + 255) / 256, 256>>>(x, xh, n4);
        n4 = (FDIM * CDIM) / 4;
        f2h<<<(n4 + 255) / 256, 256>>>(W_attn, Wah, n4);
        n4 = (CDIM * CDIM) / 4;
        f2h<<<(n4 + 255) / 256, 256>>>(W_proj, Wph, n4);
    }
    // GEMM1: fused = x * W_attn^T   [4096,6144]
    {
        dim3 grid(FDIM / 128, M / 128);
        hgemm_mma<<<grid, 256, GSMEM>>>(xh, Wah, fused, M, FDIM, CDIM);
    }
    // pack Qf/Kf
    {
        int total = BATCH * HEADS * T_SEQ * HD;
        build_qk<<<total / 256, 256>>>(fused, w_std, w_rec, Qf, Kf);
    }
    // causal attention -> fp16 att
    {
        size_t smem = (size_t)(8192 + 8192 + 8192 + 64 * 68) * sizeof(float);
        cudaFuncSetAttribute(attn_kernel,
                             cudaFuncAttributeMaxDynamicSharedMemorySize, (int)smem);
        dim3 grid(T_SEQ / 64, BATCH * HEADS);
        attn_kernel<<<grid, 256, smem>>>(Qf, Kf, fused, atth);
    }
    // GEMM2: out = att * W_proj^T   [4096,2048]
    {
        dim3 grid(CDIM / 128, M / 128);
        hgemm_mma<<<grid, 256, GSMEM>>>(atth, Wph, out, M, CDIM, CDIM);
    }
}

// round 4
// speedup vs baseline: 6.6084x; 3.1147x over previous
#include <cuda_runtime.h>
#include <cuda_fp16.h>
#include <math.h>
#include <stdint.h>

#define T_SEQ 2048
#define BATCH 2
#define CDIM  2048
#define HEADS 16
#define HD    128
#define DSTD  120
#define RLOW  8
#define FDIM  6144

// ---------------- scratch (device globals; no allocations) ----------------
__device__ float g_fused[(size_t)BATCH * T_SEQ * FDIM];
__device__ __align__(16) __half g_xh[(size_t)BATCH * T_SEQ * CDIM];
__device__ __align__(16) __half g_Wah[(size_t)FDIM * CDIM];
__device__ __align__(16) __half g_Wph[(size_t)CDIM * CDIM];
__device__ __align__(16) __half g_atth[(size_t)BATCH * T_SEQ * CDIM];
__device__ __align__(16) __half g_Qh[(size_t)BATCH * HEADS * T_SEQ * HD];
__device__ __align__(16) __half g_Kh[(size_t)BATCH * HEADS * T_SEQ * HD];
__device__ __align__(16) __half g_Vh[(size_t)BATCH * HEADS * T_SEQ * HD];

// ---------------- PTX helpers ----------------------------------------------
__device__ __forceinline__ uint32_t smem_u32(const void* p) {
    uint32_t a;
    asm("{ .reg .u64 t; cvta.to.shared.u64 t, %1; cvt.u32.u64 %0, t; }"
        : "=r"(a) : "l"(p));
    return a;
}
__device__ __forceinline__ void cp16(uint32_t saddr, const void* gaddr) {
    asm volatile("cp.async.cg.shared.global [%0], [%1], 16;"
                 :: "r"(saddr), "l"(gaddr) : "memory");
}
__device__ __forceinline__ void ldsm_x4(uint32_t* r, uint32_t addr) {
    asm volatile("ldmatrix.sync.aligned.m8n8.x4.shared.b16 {%0,%1,%2,%3}, [%4];"
                 : "=r"(r[0]), "=r"(r[1]), "=r"(r[2]), "=r"(r[3]) : "r"(addr));
}
__device__ __forceinline__ void ldsm_x4_t(uint32_t* r, uint32_t addr) {
    asm volatile("ldmatrix.sync.aligned.m8n8.x4.trans.shared.b16 {%0,%1,%2,%3}, [%4];"
                 : "=r"(r[0]), "=r"(r[1]), "=r"(r[2]), "=r"(r[3]) : "r"(addr));
}
__device__ __forceinline__ void mma16816(float* c, const uint32_t* a,
                                         uint32_t b0, uint32_t b1) {
    asm volatile(
        "mma.sync.aligned.m16n8k16.row.col.f32.f16.f16.f32 "
        "{%0,%1,%2,%3},{%4,%5,%6,%7},{%8,%9},{%0,%1,%2,%3};"
        : "+f"(c[0]), "+f"(c[1]), "+f"(c[2]), "+f"(c[3])
        : "r"(a[0]), "r"(a[1]), "r"(a[2]), "r"(a[3]), "r"(b0), "r"(b1));
}

// ---------------- HMMA GEMM: C[M,N]=A[M,K]*B[N,K]^T (fp16 in, fp32 out) ----
#define GSMEM (3 * 32768)

__global__ void __launch_bounds__(256, 2)
hgemm_mma(const __half* __restrict__ A, const __half* __restrict__ B,
          float* __restrict__ C, int M, int N, int K) {
    extern __shared__ __align__(1024) char smem_raw[];
    const uint32_t smem = smem_u32(smem_raw);
    const int tid = threadIdx.x;
    const int wid = tid >> 5;
    const int lid = tid & 31;
    const int m0 = blockIdx.y << 7;
    const int n0 = blockIdx.x << 7;
    const int wm0 = (wid & 1) << 6;
    const int wn0 = (wid >> 1) << 5;

    const int r = tid >> 1;
    const int hs = tid & 1;
    const __half* Ag = A + (size_t)(m0 + r) * K + hs * 32;
    const __half* Bg = B + (size_t)(n0 + r) * K + hs * 32;
    const uint32_t swb = r * 128 + hs * 64;

    auto load_stage = [&](int kt, int s) {
        uint32_t ab = smem + s * 32768;
        uint32_t bb = ab + 16384;
        const __half* ag = Ag + kt * 64;
        const __half* bg = Bg + kt * 64;
#pragma unroll
        for (int j = 0; j < 4; j++) {
            uint32_t off = swb + j * 16;
            uint32_t sw = off ^ ((off >> 3) & 0x70);
            cp16(ab + sw, ag + j * 8);
            cp16(bb + sw, bg + j * 8);
        }
        asm volatile("cp.async.commit_group;" ::: "memory");
    };

    float acc[4][4][4];
#pragma unroll
    for (int mt = 0; mt < 4; mt++)
#pragma unroll
        for (int nt = 0; nt < 4; nt++)
#pragma unroll
            for (int e = 0; e < 4; e++) acc[mt][nt][e] = 0.f;

    const int KT = K >> 6;
    load_stage(0, 0);
    load_stage(1, 1);

    const int grp = lid >> 3;
    const int lr = lid & 7;
    const int arow = wm0 + ((grp & 1) << 3) + lr;
    const int acol = (grp >> 1) << 3;
    const int brow = wn0 + ((grp & 1) << 3) + lr;

    for (int kt = 0; kt < KT; kt++) {
        const int s = kt % 3;
        asm volatile("cp.async.wait_group 1;" ::: "memory");
        __syncthreads();
        if (kt + 2 < KT) load_stage(kt + 2, (kt + 2) % 3);
        const uint32_t ab = smem + s * 32768;
        const uint32_t bb = ab + 16384;
#pragma unroll
        for (int ks = 0; ks < 4; ks++) {
            uint32_t a_regs[4][4];
#pragma unroll
            for (int mt = 0; mt < 4; mt++) {
                uint32_t off = (uint32_t)(arow + mt * 16) * 128 + (acol + ks * 16) * 2;
                uint32_t sw = off ^ ((off >> 3) & 0x70);
                ldsm_x4(a_regs[mt], ab + sw);
            }
            uint32_t b_regs[2][4];
#pragma unroll
            for (int np = 0; np < 2; np++) {
                uint32_t off = (uint32_t)(brow + np * 16) * 128 + (acol + ks * 16) * 2;
                uint32_t sw = off ^ ((off >> 3) & 0x70);
                ldsm_x4(b_regs[np], bb + sw);
            }
#pragma unroll
            for (int mt = 0; mt < 4; mt++)
#pragma unroll
                for (int nt = 0; nt < 4; nt++) {
                    uint32_t b0 = b_regs[nt >> 1][nt & 1];
                    uint32_t b1 = b_regs[nt >> 1][(nt & 1) + 2];
                    mma16816(acc[mt][nt], a_regs[mt], b0, b1);
                }
        }
    }

    const int row0 = m0 + wm0 + (lid >> 2);
    const int col0 = n0 + wn0 + (lid & 3) * 2;
#pragma unroll
    for (int mt = 0; mt < 4; mt++)
#pragma unroll
        for (int nt = 0; nt < 4; nt++) {
            float* p0 = C + (size_t)(row0 + mt * 16) * N + col0 + nt * 8;
            float* p1 = C + (size_t)(row0 + mt * 16 + 8) * N + col0 + nt * 8;
            *(float2*)p0 = make_float2(acc[mt][nt][0], acc[mt][nt][1]);
            *(float2*)p1 = make_float2(acc[mt][nt][2], acc[mt][nt][3]);
        }
}

// ---------------- fp32 -> fp16 conversion ----------------------------------
__global__ void f2h(const float* __restrict__ in, __half* __restrict__ out, int n4) {
    int i = blockIdx.x * blockDim.x + threadIdx.x;
    if (i < n4) {
        float4 v = ((const float4*)in)[i];
        ((__half2*)out)[2 * i] = __floats2half2_rn(v.x, v.y);
        ((__half2*)out)[2 * i + 1] = __floats2half2_rn(v.z, v.w);
    }
}

// ---------------- Build Qh/Kh/Vh (fp16, head-major, scale folded into Q) ---
__global__ void build_qkv(const float* __restrict__ fused,
                          const float* __restrict__ w_std,
                          const float* __restrict__ w_rec,
                          __half* __restrict__ Qh, __half* __restrict__ Kh,
                          __half* __restrict__ Vh) {
    int idx = blockIdx.x * blockDim.x + threadIdx.x;
    int d = idx & 127;
    int t = (idx >> 7) & (T_SEQ - 1);
    int h = (idx >> 18) & 15;
    int b = idx >> 22;

    float wsv = w_std[h];
    float wrv = w_rec[h];
    float ws = sqrtf(fmaxf(wsv, 1e-8f));
    float wr = sqrtf(fmaxf(wrv, 1e-8f));
    bool ra = (wrv > 0.1f);
    const float scale = 0.08838834764831845f;  // 1/sqrt(128)

    size_t frow = ((size_t)(b * T_SEQ + t)) * FDIM;
    float q, k;
    if (d < DSTD) {
        q = ws * fused[frow + h * DSTD + d];
        k = ws * fused[frow + (HEADS * DSTD) + h * DSTD + d];
    } else {
        int rr = d - DSTD;
        float ql = fused[frow + 5888 + h * RLOW + rr];
        float kl = fused[frow + 6016 + h * RLOW + rr];
        q = ra ? wr * kl : ws * ql;
        k = ra ? wr * ql : ws * kl;
    }
    Qh[idx] = __float2half(q * scale);
    Kh[idx] = __float2half(k);
    Vh[idx] = __float2half(fused[frow + 3840 + h * HD + d]);
}

// ---------------- HMMA causal flash attention ------------------------------
#define ASMEM 65536
__device__ __forceinline__ uint32_t swoff(int row, int c16) {
    return (uint32_t)row * 256 + (uint32_t)((c16 ^ (row & 7)) * 16);
}

__global__ void __launch_bounds__(128)
attn_mma(const __half* __restrict__ Qh, const __half* __restrict__ Kh,
         const __half* __restrict__ Vh, __half* __restrict__ out) {
    extern __shared__ __align__(1024) char smem_raw[];
    const uint32_t sb = smem_u32(smem_raw);
    const int tid = threadIdx.x;
    const int wid = tid >> 5;
    const int lid = tid & 31;
    const int grp = lid >> 3;
    const int lr = lid & 7;
    const int bh = blockIdx.y;
    const int b = bh >> 4;
    const int h = bh & 15;
    const int q0 = blockIdx.x << 6;
    const int nkt = blockIdx.x + 1;

    // ---- Q tile -> stage-0 buffer -> register fragments
    const __half* Qg = Qh + ((size_t)bh * T_SEQ + q0) * HD;
#pragma unroll
    for (int i = 0; i < 8; i++) {
        int idx = tid + i * 128;
        int row = idx >> 4;
        int c = idx & 15;
        cp16(sb + swoff(row, c), Qg + (size_t)row * HD + c * 8);
    }
    asm volatile("cp.async.commit_group;" ::: "memory");
    asm volatile("cp.async.wait_group 0;" ::: "memory");
    __syncthreads();

    uint32_t qf[8][4];
    {
        int arow = (wid << 4) + ((grp & 1) << 3) + lr;
        int ach = (grp >> 1);
#pragma unroll
        for (int ks = 0; ks < 8; ks++)
            ldsm_x4(qf[ks], sb + swoff(arow, ks * 2 + ach));
    }
    __syncthreads();

    auto load_kv = [&](int kt, int s) {
        const __half* Kg = Kh + ((size_t)bh * T_SEQ + kt * 64) * HD;
        const __half* Vg = Vh + ((size_t)bh * T_SEQ + kt * 64) * HD;
        uint32_t kb = sb + (uint32_t)s * 32768;
        uint32_t vb = kb + 16384;
#pragma unroll
        for (int i = 0; i < 8; i++) {
            int idx = tid + i * 128;
            int row = idx >> 4;
            int c = idx & 15;
            uint32_t o = swoff(row, c);
            cp16(kb + o, Kg + (size_t)row * HD + c * 8);
            cp16(vb + o, Vg + (size_t)row * HD + c * 8);
        }
        asm volatile("cp.async.commit_group;" ::: "memory");
    };

    float oa[16][4];
#pragma unroll
    for (int ot = 0; ot < 16; ot++)
#pragma unroll
        for (int e = 0; e < 4; e++) oa[ot][e] = 0.f;
    float m0 = -1e30f, m1 = -1e30f, l0 = 0.f, l1 = 0.f;

    load_kv(0, 0);
    if (nkt > 1) load_kv(1, 1);

    for (int kt = 0; kt < nkt; kt++) {
        const int s = kt & 1;
        if (kt + 1 < nkt)
            asm volatile("cp.async.wait_group 1;" ::: "memory");
        else
            asm volatile("cp.async.wait_group 0;" ::: "memory");
        __syncthreads();

        const uint32_t kb = sb + (uint32_t)s * 32768;
        const uint32_t vb = kb + 16384;

        float sa[8][4];
#pragma unroll
        for (int nt = 0; nt < 8; nt++)
#pragma unroll
            for (int e = 0; e < 4; e++) sa[nt][e] = 0.f;

        const int brb = ((grp & 1) << 3) + lr;
        const int bch = (grp >> 1);
#pragma unroll
        for (int ks = 0; ks < 8; ks++) {
            uint32_t br[4][4];
#pragma unroll
            for (int np = 0; np < 4; np++)
                ldsm_x4(br[np], kb + swoff(np * 16 + brb, ks * 2 + bch));
#pragma unroll
            for (int nt = 0; nt < 8; nt++)
                mma16816(sa[nt], qf[ks], br[nt >> 1][nt & 1], br[nt >> 1][(nt & 1) + 2]);
        }

        if (kt == blockIdx.x) {
            int qr = (wid << 4) + (lid >> 2);
#pragma unroll
            for (int nt = 0; nt < 8; nt++) {
                int cb = nt * 8 + ((lid & 3) << 1);
#pragma unroll
                for (int e = 0; e < 4; e++) {
                    int col = cb + (e & 1);
                    int row = qr + ((e >> 1) << 3);
                    if (col > row) sa[nt][e] = -1e30f;
                }
            }
        }

        float mx0 = -1e30f, mx1 = -1e30f;
#pragma unroll
        for (int nt = 0; nt < 8; nt++) {
            mx0 = fmaxf(mx0, fmaxf(sa[nt][0], sa[nt][1]));
            mx1 = fmaxf(mx1, fmaxf(sa[nt][2], sa[nt][3]));
        }
        mx0 = fmaxf(mx0, __shfl_xor_sync(0xffffffffu, mx0, 1));
        mx0 = fmaxf(mx0, __shfl_xor_sync(0xffffffffu, mx0, 2));
        mx1 = fmaxf(mx1, __shfl_xor_sync(0xffffffffu, mx1, 1));
        mx1 = fmaxf(mx1, __shfl_xor_sync(0xffffffffu, mx1, 2));

        float mn0 = fmaxf(m0, mx0), mn1 = fmaxf(m1, mx1);
        float al0 = __expf(m0 - mn0), al1 = __expf(m1 - mn1);
        m0 = mn0; m1 = mn1;

        float sum0 = 0.f, sum1 = 0.f;
        uint32_t pf[8][2];
#pragma unroll
        for (int nt = 0; nt < 8; nt++) {
            float p0 = __expf(sa[nt][0] - mn0);
            float p1 = __expf(sa[nt][1] - mn0);
            float p2 = __expf(sa[nt][2] - mn1);
            float p3 = __expf(sa[nt][3] - mn1);
            sum0 += p0 + p1; sum1 += p2 + p3;
            __half2 h01 = __floats2half2_rn(p0, p1);
            __half2 h23 = __floats2half2_rn(p2, p3);
            pf[nt][0] = *(uint32_t*)&h01;
            pf[nt][1] = *(uint32_t*)&h23;
        }
        sum0 += __shfl_xor_sync(0xffffffffu, sum0, 1);
        sum0 += __shfl_xor_sync(0xffffffffu, sum0, 2);
        sum1 += __shfl_xor_sync(0xffffffffu, sum1, 1);
        sum1 += __shfl_xor_sync(0xffffffffu, sum1, 2);
        l0 = l0 * al0 + sum0;
        l1 = l1 * al1 + sum1;

#pragma unroll
        for (int ot = 0; ot < 16; ot++) {
            oa[ot][0] *= al0; oa[ot][1] *= al0;
            oa[ot][2] *= al1; oa[ot][3] *= al1;
        }

#pragma unroll
        for (int kp = 0; kp < 4; kp++) {
            uint32_t av[4] = {pf[2 * kp][0], pf[2 * kp][1],
                              pf[2 * kp + 1][0], pf[2 * kp + 1][1]};
#pragma unroll
            for (int db = 0; db < 8; db++) {
                uint32_t vr[4];
                ldsm_x4_t(vr, vb + swoff(kp * 16 + ((grp & 1) << 3) + lr, db * 2 + (grp >> 1)));
                mma16816(oa[db * 2], av, vr[0], vr[1]);
                mma16816(oa[db * 2 + 1], av, vr[2], vr[3]);
            }
        }

        __syncthreads();
        if (kt + 2 < nkt) load_kv(kt + 2, s);
    }

    float inv0 = 1.f / l0, inv1 = 1.f / l1;
    int qr = q0 + (wid << 4) + (lid >> 2);
    __half* ob0 = out + ((size_t)(b * T_SEQ + qr)) * CDIM + h * HD;
    __half* ob1 = out + ((size_t)(b * T_SEQ + qr + 8)) * CDIM + h * HD;
#pragma unroll
    for (int ot = 0; ot < 16; ot++) {
        int col = ot * 8 + ((lid & 3) << 1);
        *(__half2*)(ob0 + col) = __floats2half2_rn(oa[ot][0] * inv0, oa[ot][1] * inv0);
        *(__half2*)(ob1 + col) = __floats2half2_rn(oa[ot][2] * inv1, oa[ot][3] * inv1);
    }
}

// ---------------- launch ----------------------------------------------------
extern "C" void kernel_launch(void* const* d_in, const int* in_sizes, int n_in,
                              void* d_out, int out_size) {
    const float* x      = (const float*)d_in[0];
    const float* W_attn = (const float*)d_in[1];
    const float* W_proj = (const float*)d_in[2];
    const float* w_std  = (const float*)d_in[3];
    const float* w_rec  = (const float*)d_in[4];
    float* out = (float*)d_out;

    float* fused;
    __half *xh, *Wah, *Wph, *atth, *Qh, *Kh, *Vh;
    cudaGetSymbolAddress((void**)&fused, g_fused);
    cudaGetSymbolAddress((void**)&xh, g_xh);
    cudaGetSymbolAddress((void**)&Wah, g_Wah);
    cudaGetSymbolAddress((void**)&Wph, g_Wph);
    cudaGetSymbolAddress((void**)&atth, g_atth);
    cudaGetSymbolAddress((void**)&Qh, g_Qh);
    cudaGetSymbolAddress((void**)&Kh, g_Kh);
    cudaGetSymbolAddress((void**)&Vh, g_Vh);

    const int M = BATCH * T_SEQ;  // 4096

    cudaFuncSetAttribute(hgemm_mma, cudaFuncAttributeMaxDynamicSharedMemorySize, GSMEM);
    cudaFuncSetAttribute(attn_mma, cudaFuncAttributeMaxDynamicSharedMemorySize, ASMEM);

    {
        int n4 = (M * CDIM) / 4;
        f2h<<<(n4 + 255) / 256, 256>>>(x, xh, n4);
        n4 = (FDIM * CDIM) / 4;
        f2h<<<(n4 + 255) / 256, 256>>>(W_attn, Wah, n4);
        n4 = (CDIM * CDIM) / 4;
        f2h<<<(n4 + 255) / 256, 256>>>(W_proj, Wph, n4);
    }
    {
        dim3 grid(FDIM / 128, M / 128);
        hgemm_mma<<<grid, 256, GSMEM>>>(xh, Wah, fused, M, FDIM, CDIM);
    }
    {
        int total = BATCH * HEADS * T_SEQ * HD;
        build_qkv<<<total / 256, 256>>>(fused, w_std, w_rec, Qh, Kh, Vh);
    }
    {
        dim3 grid(T_SEQ / 64, BATCH * HEADS);
        attn_mma<<<grid, 128, ASMEM>>>(Qh, Kh, Vh, atth);
    }
    {
        dim3 grid(CDIM / 128, M / 128);
        hgemm_mma<<<grid, 256, GSMEM>>>(atth, Wph, out, M, CDIM, CDIM);
    }
}